// round 10
// baseline (speedup 1.0000x reference)
#include <cuda_runtime.h>
#include <math.h>

#define HID 1024
#define EMB 1024
#define MAXLEN 4096
#define VOCAB 50257
#define NBLK 148
#define NTHR 1024
#define NPART 8
#define NWARPS (NBLK * 32)    // 4736 warps
#define SPLIT 12288           // fc2 rows < SPLIT load with default policy (L2-pinned)

// ---------------- device scratch ----------------
__device__ float g_hnew[HID];
__device__ float g_scores[MAXLEN];
__device__ float g_ctx_part[NPART * HID];
__device__ float g_hid[HID];
__device__ float g_lse_m[NBLK];
__device__ float g_lse_l[NBLK];
__device__ unsigned long long g_bar = 0ULL;   // monotonic ticket counter (never reset)

__device__ __forceinline__ float warp_sum(float v) {
#pragma unroll
    for (int o = 16; o; o >>= 1) v += __shfl_down_sync(0xffffffffu, v, o);
    return v;
}
__device__ __forceinline__ float warp_max(float v) {
#pragma unroll
    for (int o = 16; o; o >>= 1) v = fmaxf(v, __shfl_down_sync(0xffffffffu, v, o));
    return v;
}

// deterministic, reset-free grid barrier (148 blocks, 1/SM, co-resident)
__device__ __forceinline__ void grid_barrier() {
    __syncthreads();
    if (threadIdx.x == 0) {
        __threadfence();
        unsigned long long ticket = atomicAdd(&g_bar, 1ULL);
        unsigned long long target = (ticket / NBLK + 1ULL) * (unsigned long long)NBLK;
        while (*(volatile unsigned long long*)&g_bar < target) { }
    }
    __syncthreads();
}

// dot of one 4KB row against smem vector; default cache policy (L2-allocating)
__device__ __forceinline__ float dot_row_pin(const float4* __restrict__ p,
                                             const float4* __restrict__ h4, int lane) {
    float a = 0.f;
#pragma unroll
    for (int k = lane; k < 256; k += 32) {
        float4 v = p[k], hv = h4[k];
        a += v.x * hv.x + v.y * hv.y + v.z * hv.z + v.w * hv.w;
    }
    return a;
}
// same but streaming (evict-first in L2)
__device__ __forceinline__ float dot_row_cs(const float4* __restrict__ p,
                                            const float4* __restrict__ h4, int lane) {
    float a = 0.f;
#pragma unroll
    for (int k = lane; k < 256; k += 32) {
        float4 v = __ldcs(p + k);
        float4 hv = h4[k];
        a += v.x * hv.x + v.y * hv.y + v.z * hv.z + v.w * hv.w;
    }
    return a;
}

__global__ __launch_bounds__(NTHR, 1)
void fused_all(const float* __restrict__ A, const float* __restrict__ x,
               const float* __restrict__ h, const float* __restrict__ c,
               const float* __restrict__ W_ih, const float* __restrict__ W_hh,
               const float* __restrict__ b_ih, const float* __restrict__ b_hh,
               const float* __restrict__ fc1_w, const float* __restrict__ fc1_b,
               const float* __restrict__ fc2_w, const float* __restrict__ fc2_b,
               float* __restrict__ out)
{
    __shared__ __align__(16) float svec[2 * HID];  // 8 KB staging
    __shared__ __align__(16) float sws[512];       // softmax weights
    __shared__ float sred[16][64];                 // ctx / fc1 partial reduce
    __shared__ float sgate[4][8];
    __shared__ float sredw[32];
    __shared__ float sredw2[32];

    const int tid = threadIdx.x;
    const int b = blockIdx.x;
    const int w = tid >> 5, lane = tid & 31;

    // ================= Phase 1: LSTM (blocks 0..127; default cache -> W pinned in L2) =================
    if (b < 128) {
        svec[tid] = x[tid];
        svec[HID + tid] = h[tid];
        __syncthreads();
        {
            int jl = w & 7, g = w >> 3;              // 8 hidden units, 4 gates per block
            int j = b * 8 + jl;
            int row = g * HID + j;
            const float4* rW = (const float4*)(W_ih + (size_t)row * EMB);
            const float4* rU = (const float4*)(W_hh + (size_t)row * HID);
            const float4* x4 = (const float4*)svec;
            const float4* h4 = (const float4*)(svec + HID);
            float a = dot_row_pin(rW, x4, lane) + dot_row_pin(rU, h4, lane);
            a = warp_sum(a);
            if (lane == 0) sgate[g][jl] = a;
        }
        __syncthreads();
        if (tid < 8) {
            int j = b * 8 + tid;
            float gi = sgate[0][tid] + b_ih[j]           + b_hh[j];
            float gf = sgate[1][tid] + b_ih[HID + j]     + b_hh[HID + j];
            float gg = sgate[2][tid] + b_ih[2 * HID + j] + b_hh[2 * HID + j];
            float go = sgate[3][tid] + b_ih[3 * HID + j] + b_hh[3 * HID + j];
            float ig = 1.f / (1.f + expf(-gi));
            float fg = 1.f / (1.f + expf(-gf));
            float gt = tanhf(gg);
            float og = 1.f / (1.f + expf(-go));
            float cn = fg * c[j] + ig * gt;
            float hn = og * tanhf(cn);
            g_hnew[j] = hn;
            out[VOCAB + j] = hn;
            out[VOCAB + HID + j] = cn;
        }
    }
    grid_barrier();

    // ================= Phase 2: scores[t] = A[t,:] . h_new (all blocks; A pinned) =================
    {
        svec[tid] = g_hnew[tid];
        __syncthreads();
        int t = b * 32 + w;                      // 0..4735
        if (t < MAXLEN) {
            const float4* r = (const float4*)(A + (size_t)t * HID);
            float a = dot_row_pin(r, (const float4*)svec, lane);
            a = warp_sum(a);
            if (lane == 0) g_scores[t] = a;
        }
    }
    grid_barrier();

    // ================= Phase 3: softmax stats (redundant per block) + ctx partials (blocks 0..127) =================
    if (b < 128) {
        float m, inv_l;
        {
            float mm = -INFINITY;
#pragma unroll
            for (int i = 0; i < 4; i++) mm = fmaxf(mm, g_scores[tid + i * 1024]);
            mm = warp_max(mm);
            if (lane == 0) sredw[w] = mm;
            __syncthreads();
            if (w == 0) {
                float v = sredw[lane];
                v = warp_max(v);
                if (lane == 0) sredw[0] = v;
            }
            __syncthreads();
            m = sredw[0];
            __syncthreads();

            float l = 0.f;
#pragma unroll
            for (int i = 0; i < 4; i++) l += expf(g_scores[tid + i * 1024] - m);
            l = warp_sum(l);
            if (lane == 0) sredw2[w] = l;
            __syncthreads();
            if (w == 0) {
                float v = sredw2[lane];
                v = warp_sum(v);
                if (lane == 0) sredw2[0] = 1.f / v;
            }
            __syncthreads();
            inv_l = sredw2[0];
        }
        {
            int bt = b >> 4;                         // t-chunk 0..7 (512 t each)
            int bd = b & 15;                         // d-chunk 0..15 (64 d each)
            int t0 = bt * 512;
            if (tid < 512) sws[tid] = expf(g_scores[t0 + tid] - m) * inv_l;
            __syncthreads();

            int tsub = tid >> 6;                     // 0..15, 32 t each
            int dl = tid & 63;
            int d = bd * 64 + dl;
            float acc = 0.f;
            int tb = tsub * 32;
#pragma unroll 4
            for (int t = 0; t < 32; t++)
                acc += A[(size_t)(t0 + tb + t) * HID + d] * sws[tb + t];
            sred[tsub][dl] = acc;
            __syncthreads();
            if (tid < 64) {
                float v = 0.f;
#pragma unroll
                for (int k2 = 0; k2 < 16; k2++) v += sred[k2][tid];
                g_ctx_part[bt * HID + bd * 64 + tid] = v;
            }
        }
    }
    grid_barrier();

    // ================= Phase 4: fc1 (fused ctx reduce; blocks 0..127; fc1_w pinned) =================
    if (b < 128) {
        float4* sc4 = (float4*)svec;
        if (tid < 256) {
            const float4* part4 = (const float4*)g_ctx_part;
            float4 a = part4[tid];
#pragma unroll
            for (int s = 1; s < NPART; s++) {
                float4 p = part4[s * 256 + tid];
                a.x += p.x; a.y += p.y; a.z += p.z; a.w += p.w;
            }
            sc4[tid] = a;
        } else if (tid < 512) {
            sc4[tid] = ((const float4*)g_hnew)[tid - 256];
        }
        __syncthreads();

        int jl = w >> 2;                         // row within block 0..7
        int q = w & 3;                           // quarter of K
        int j = b * 8 + jl;
        const float4* r = (const float4*)(fc1_w + (size_t)j * 2 * HID);
        float a = 0.f;
#pragma unroll
        for (int k = q * 128 + lane; k < (q + 1) * 128; k += 32) {
            float4 v = r[k], cv = sc4[k];
            a += v.x * cv.x + v.y * cv.y + v.z * cv.z + v.w * cv.w;
        }
        a = warp_sum(a);
        if (lane == 0) sred[0][w] = a;
        __syncthreads();
        if (tid < 8) {
            float v = sred[0][tid * 4] + sred[0][tid * 4 + 1] +
                      sred[0][tid * 4 + 2] + sred[0][tid * 4 + 3];
            g_hid[b * 8 + tid] = v + fc1_b[b * 8 + tid];
        }
    }
    grid_barrier();

    // ================= Phase 5: fc2 (2 rows/warp; rows<SPLIT pinned, rest streaming) + LSE =================
    {
        svec[tid] = g_hid[tid];
        __syncthreads();
        const float4* h4 = (const float4*)svec;
        int gw = b * 32 + w;                     // global warp 0..4735
        float lm = -INFINITY, ll = 0.f;
        for (int r0 = gw; r0 < VOCAB; r0 += 2 * NWARPS) {
            int r1 = r0 + NWARPS;
            bool has1 = (r1 < VOCAB);
            const float4* p0 = (const float4*)(fc2_w + (size_t)r0 * HID);
            const float4* p1 = (const float4*)(fc2_w + (size_t)(has1 ? r1 : r0) * HID);
            float a0 = (r0 < SPLIT) ? dot_row_pin(p0, h4, lane) : dot_row_cs(p0, h4, lane);
            float a1 = (r1 < SPLIT) ? dot_row_pin(p1, h4, lane) : dot_row_cs(p1, h4, lane);
            a0 = warp_sum(a0);
            a1 = warp_sum(a1);
            if (lane == 0) {
                float logit0 = a0 + fc2_b[r0];
                out[r0] = logit0;
                float mm = fmaxf(lm, logit0);
                ll = ll * expf(lm - mm) + expf(logit0 - mm);
                lm = mm;
                if (has1) {
                    float logit1 = a1 + fc2_b[r1];
                    out[r1] = logit1;
                    mm = fmaxf(lm, logit1);
                    ll = ll * expf(lm - mm) + expf(logit1 - mm);
                    lm = mm;
                }
            }
        }
        if (lane == 0) { sredw[w] = lm; sredw2[w] = ll; }
        __syncthreads();
        if (w == 0) {
            float mm = sredw[lane], lll = sredw2[lane];
#pragma unroll
            for (int o = 16; o; o >>= 1) {
                float m2 = __shfl_down_sync(0xffffffffu, mm, o);
                float l2 = __shfl_down_sync(0xffffffffu, lll, o);
                float M = fmaxf(mm, m2);
                lll = lll * expf(mm - M) + l2 * expf(m2 - M);
                mm = M;
            }
            if (lane == 0) { g_lse_m[b] = mm; g_lse_l[b] = lll; }
        }
    }
    grid_barrier();

    // ================= Phase 6: LSE combine (redundant per block) + float4 subtract =================
    {
        if (w == 0) {
            float mm = -INFINITY, lll = 0.f;
            for (int i = lane; i < NBLK; i += 32) {
                float m2 = g_lse_m[i], l2 = g_lse_l[i];
                float M = fmaxf(mm, m2);
                lll = lll * expf(mm - M) + l2 * expf(m2 - M);
                mm = M;
            }
#pragma unroll
            for (int o = 16; o; o >>= 1) {
                float m2 = __shfl_down_sync(0xffffffffu, mm, o);
                float l2 = __shfl_down_sync(0xffffffffu, lll, o);
                float M = fmaxf(mm, m2);
                lll = lll * expf(mm - M) + l2 * expf(m2 - M);
                mm = M;
            }
            if (lane == 0) sredw[0] = mm + logf(lll);
        }
        __syncthreads();
        float lse = sredw[0];
        const int N4 = VOCAB / 4;                // 12564
        int i4 = b * NTHR + tid;
        float4* o4 = (float4*)out;
        if (i4 < N4) {
            float4 v = o4[i4];
            v.x -= lse; v.y -= lse; v.z -= lse; v.w -= lse;
            o4[i4] = v;
        } else if (i4 == N4) {
            out[VOCAB - 1] -= lse;               // tail element
        }
    }
}

// ---------------- launch ----------------
extern "C" void kernel_launch(void* const* d_in, const int* in_sizes, int n_in,
                              void* d_out, int out_size) {
    const float* attn  = (const float*)d_in[0];
    const float* x     = (const float*)d_in[1];
    const float* h     = (const float*)d_in[2];
    const float* c     = (const float*)d_in[3];
    const float* W_ih  = (const float*)d_in[4];
    const float* W_hh  = (const float*)d_in[5];
    const float* b_ih  = (const float*)d_in[6];
    const float* b_hh  = (const float*)d_in[7];
    const float* fc1_w = (const float*)d_in[8];
    const float* fc1_b = (const float*)d_in[9];
    const float* fc2_w = (const float*)d_in[10];
    const float* fc2_b = (const float*)d_in[11];
    float* out = (float*)d_out;

    fused_all<<<NBLK, NTHR>>>(attn, x, h, c, W_ih, W_hh, b_ih, b_hh,
                              fc1_w, fc1_b, fc2_w, fc2_b, out);
}

// round 11
// speedup vs baseline: 1.0708x; 1.0708x over previous
#include <cuda_runtime.h>
#include <math.h>

#define HID 1024
#define EMB 1024
#define MAXLEN 4096
#define VOCAB 50257
#define NBLK 148
#define NTHR 1024
#define NPART 8
#define NWARPS (NBLK * 32)    // 4736 warps

// ---------------- device scratch ----------------
__device__ float g_gates[4 * HID];
__device__ float g_scores[MAXLEN];
__device__ float g_ctx_part[NPART * HID];
__device__ float g_hid[HID];
__device__ float g_lse_m[NBLK];
__device__ float g_lse_l[NBLK];
__device__ unsigned long long g_bar = 0ULL;   // monotonic ticket counter (never reset)

__device__ __forceinline__ float warp_sum(float v) {
#pragma unroll
    for (int o = 16; o; o >>= 1) v += __shfl_down_sync(0xffffffffu, v, o);
    return v;
}
__device__ __forceinline__ float warp_max(float v) {
#pragma unroll
    for (int o = 16; o; o >>= 1) v = fmaxf(v, __shfl_down_sync(0xffffffffu, v, o));
    return v;
}

// deterministic, reset-free grid barrier (148 blocks, 1/SM, co-resident)
__device__ __forceinline__ void grid_barrier() {
    __syncthreads();
    if (threadIdx.x == 0) {
        __threadfence();
        unsigned long long ticket = atomicAdd(&g_bar, 1ULL);
        unsigned long long target = (ticket / NBLK + 1ULL) * (unsigned long long)NBLK;
        while (*(volatile unsigned long long*)&g_bar < target) { }
    }
    __syncthreads();
}

__global__ __launch_bounds__(NTHR, 1)
void fused_all(const float* __restrict__ A, const float* __restrict__ x,
               const float* __restrict__ h, const float* __restrict__ c,
               const float* __restrict__ W_ih, const float* __restrict__ W_hh,
               const float* __restrict__ b_ih, const float* __restrict__ b_hh,
               const float* __restrict__ fc1_w, const float* __restrict__ fc1_b,
               const float* __restrict__ fc2_w, const float* __restrict__ fc2_b,
               float* __restrict__ out)
{
    __shared__ __align__(16) float svec[2 * HID];   // 8 KB staging
    __shared__ __align__(16) float shnew[HID];      // block-local h_new (persists ph2->ph4)
    __shared__ __align__(16) float sws[512];        // softmax weights
    __shared__ float sred[16][64];                  // ctx / fc1 partial reduce
    __shared__ float sredw[32];
    __shared__ float sredw2[32];

    const int tid = threadIdx.x;
    const int b = blockIdx.x;
    const int w = tid >> 5, lane = tid & 31;

    // ================= Phase 1: gate-row GEMV across ALL 148 blocks =================
    {
        svec[tid] = x[tid];
        svec[HID + tid] = h[tid];
        __syncthreads();
        int r = w * NBLK + b;                    // 0..4735, gate-row
        if (r < 4 * HID) {
            const float4* rW = (const float4*)(W_ih + (size_t)r * EMB);
            const float4* rU = (const float4*)(W_hh + (size_t)r * HID);
            const float4* x4 = (const float4*)svec;
            const float4* h4 = (const float4*)(svec + HID);
            float a = 0.f;
#pragma unroll
            for (int k = lane; k < 256; k += 32) {
                float4 wv = __ldcs(rW + k), xv = x4[k];
                a += wv.x * xv.x + wv.y * xv.y + wv.z * xv.z + wv.w * xv.w;
                float4 uv = __ldcs(rU + k), hv = h4[k];
                a += uv.x * hv.x + uv.y * hv.y + uv.z * hv.z + uv.w * hv.w;
            }
            a = warp_sum(a);
            if (lane == 0) g_gates[r] = a;
        }
    }
    grid_barrier();

    // ================= Phase 2a: LSTM pointwise, redundant per block -> shnew =================
    {
        int j = tid;
        float gi = g_gates[j]           + b_ih[j]           + b_hh[j];
        float gf = g_gates[HID + j]     + b_ih[HID + j]     + b_hh[HID + j];
        float gg = g_gates[2 * HID + j] + b_ih[2 * HID + j] + b_hh[2 * HID + j];
        float go = g_gates[3 * HID + j] + b_ih[3 * HID + j] + b_hh[3 * HID + j];
        float ig = 1.f / (1.f + expf(-gi));
        float fg = 1.f / (1.f + expf(-gf));
        float gt = tanhf(gg);
        float og = 1.f / (1.f + expf(-go));
        float cn = fg * c[j] + ig * gt;
        float hn = og * tanhf(cn);
        shnew[j] = hn;
        if (b == 0) {
            out[VOCAB + j] = hn;          // h_new
            out[VOCAB + HID + j] = cn;    // c_new
        }
        __syncthreads();
    }

    // ================= Phase 2b: scores[t] = A[t,:] . h_new (all 148 blocks) =================
    {
        int t = w * NBLK + b;                    // 0..4735
        if (t < MAXLEN) {
            const float4* r = (const float4*)(A + (size_t)t * HID);
            const float4* h4 = (const float4*)shnew;
            float a = 0.f;
#pragma unroll
            for (int k = lane; k < 256; k += 32) {
                float4 v = r[k], hv = h4[k];
                a += v.x * hv.x + v.y * hv.y + v.z * hv.z + v.w * hv.w;
            }
            a = warp_sum(a);
            if (lane == 0) g_scores[t] = a;
        }
    }
    grid_barrier();

    // ================= Phase 3: softmax stats (redundant per block) + ctx partials (blocks 0..127) =================
    if (b < 128) {
        float m, inv_l;
        {
            float mm = -INFINITY;
#pragma unroll
            for (int i = 0; i < 4; i++) mm = fmaxf(mm, g_scores[tid + i * 1024]);
            mm = warp_max(mm);
            if (lane == 0) sredw[w] = mm;
            __syncthreads();
            if (w == 0) {
                float v = sredw[lane];
                v = warp_max(v);
                if (lane == 0) sredw[0] = v;
            }
            __syncthreads();
            m = sredw[0];
            __syncthreads();

            float l = 0.f;
#pragma unroll
            for (int i = 0; i < 4; i++) l += expf(g_scores[tid + i * 1024] - m);
            l = warp_sum(l);
            if (lane == 0) sredw2[w] = l;
            __syncthreads();
            if (w == 0) {
                float v = sredw2[lane];
                v = warp_sum(v);
                if (lane == 0) sredw2[0] = 1.f / v;
            }
            __syncthreads();
            inv_l = sredw2[0];
        }
        {
            int bt = b >> 4;                         // t-chunk 0..7 (512 t each)
            int bd = b & 15;                         // d-chunk 0..15 (64 d each)
            int t0 = bt * 512;
            if (tid < 512) sws[tid] = expf(g_scores[t0 + tid] - m) * inv_l;
            __syncthreads();

            int tsub = tid >> 6;                     // 0..15, 32 t each
            int dl = tid & 63;
            int d = bd * 64 + dl;
            float acc = 0.f;
            int tb = tsub * 32;
#pragma unroll 4
            for (int t = 0; t < 32; t++)
                acc += A[(size_t)(t0 + tb + t) * HID + d] * sws[tb + t];
            sred[tsub][dl] = acc;
            __syncthreads();
            if (tid < 64) {
                float v = 0.f;
#pragma unroll
                for (int k2 = 0; k2 < 16; k2++) v += sred[k2][tid];
                g_ctx_part[bt * HID + bd * 64 + tid] = v;
            }
        }
    }
    grid_barrier();

    // ================= Phase 4: fc1 (fused ctx reduce; blocks 0..127, 8 rows each) =================
    if (b < 128) {
        float4* sc4 = (float4*)svec;
        if (tid < 256) {
            const float4* part4 = (const float4*)g_ctx_part;
            float4 a = part4[tid];
#pragma unroll
            for (int s = 1; s < NPART; s++) {
                float4 p = part4[s * 256 + tid];
                a.x += p.x; a.y += p.y; a.z += p.z; a.w += p.w;
            }
            sc4[tid] = a;
        } else if (tid < 512) {
            sc4[tid] = ((const float4*)shnew)[tid - 256];   // smem->smem, no global
        }
        __syncthreads();

        int jl = w >> 2;                         // row within block 0..7
        int q = w & 3;                           // quarter of K
        int j = b * 8 + jl;
        const float4* r = (const float4*)(fc1_w + (size_t)j * 2 * HID);
        float a = 0.f;
#pragma unroll
        for (int k = q * 128 + lane; k < (q + 1) * 128; k += 32) {
            float4 v = __ldcs(r + k), cv = sc4[k];
            a += v.x * cv.x + v.y * cv.y + v.z * cv.z + v.w * cv.w;
        }
        a = warp_sum(a);
        if (lane == 0) sred[0][w] = a;
        __syncthreads();
        if (tid < 8) {
            float v = sred[0][tid * 4] + sred[0][tid * 4 + 1] +
                      sred[0][tid * 4 + 2] + sred[0][tid * 4 + 3];
            g_hid[b * 8 + tid] = v + fc1_b[b * 8 + tid];
        }
    }
    grid_barrier();

    // ================= Phase 5: fc2 (2 rows/warp, streaming loads) + per-block LSE =================
    {
        svec[tid] = g_hid[tid];
        __syncthreads();
        const float4* h4 = (const float4*)svec;
        int gw = b * 32 + w;                     // global warp 0..4735
        float lm = -INFINITY, ll = 0.f;
        for (int r0 = gw; r0 < VOCAB; r0 += 2 * NWARPS) {
            int r1 = r0 + NWARPS;
            bool has1 = (r1 < VOCAB);
            const float4* p0 = (const float4*)(fc2_w + (size_t)r0 * HID);
            const float4* p1 = (const float4*)(fc2_w + (size_t)(has1 ? r1 : r0) * HID);
            float a0 = 0.f, a1 = 0.f;
#pragma unroll
            for (int k = lane; k < 256; k += 32) {
                float4 v0 = __ldcs(p0 + k);
                float4 v1 = __ldcs(p1 + k);
                float4 hv = h4[k];
                a0 += v0.x * hv.x + v0.y * hv.y + v0.z * hv.z + v0.w * hv.w;
                a1 += v1.x * hv.x + v1.y * hv.y + v1.z * hv.z + v1.w * hv.w;
            }
            a0 = warp_sum(a0);
            a1 = warp_sum(a1);
            if (lane == 0) {
                float logit0 = a0 + fc2_b[r0];
                out[r0] = logit0;
                float mm = fmaxf(lm, logit0);
                ll = ll * expf(lm - mm) + expf(logit0 - mm);
                lm = mm;
                if (has1) {
                    float logit1 = a1 + fc2_b[r1];
                    out[r1] = logit1;
                    mm = fmaxf(lm, logit1);
                    ll = ll * expf(lm - mm) + expf(logit1 - mm);
                    lm = mm;
                }
            }
        }
        if (lane == 0) { sredw[w] = lm; sredw2[w] = ll; }
        __syncthreads();
        if (w == 0) {
            float mm = sredw[lane], lll = sredw2[lane];
#pragma unroll
            for (int o = 16; o; o >>= 1) {
                float m2 = __shfl_down_sync(0xffffffffu, mm, o);
                float l2 = __shfl_down_sync(0xffffffffu, lll, o);
                float M = fmaxf(mm, m2);
                lll = lll * expf(mm - M) + l2 * expf(m2 - M);
                mm = M;
            }
            if (lane == 0) { g_lse_m[b] = mm; g_lse_l[b] = lll; }
        }
    }
    grid_barrier();

    // ================= Phase 6: LSE combine (redundant per block) + float4 subtract =================
    {
        if (w == 0) {
            float mm = -INFINITY, lll = 0.f;
            for (int i = lane; i < NBLK; i += 32) {
                float m2 = g_lse_m[i], l2 = g_lse_l[i];
                float M = fmaxf(mm, m2);
                lll = lll * expf(mm - M) + l2 * expf(m2 - M);
                mm = M;
            }
#pragma unroll
            for (int o = 16; o; o >>= 1) {
                float m2 = __shfl_down_sync(0xffffffffu, mm, o);
                float l2 = __shfl_down_sync(0xffffffffu, lll, o);
                float M = fmaxf(mm, m2);
                lll = lll * expf(mm - M) + l2 * expf(m2 - M);
                mm = M;
            }
            if (lane == 0) sredw[0] = mm + logf(lll);
        }
        __syncthreads();
        float lse = sredw[0];
        const int N4 = VOCAB / 4;                // 12564
        int i4 = b * NTHR + tid;
        float4* o4 = (float4*)out;
        if (i4 < N4) {
            float4 v = o4[i4];
            v.x -= lse; v.y -= lse; v.z -= lse; v.w -= lse;
            o4[i4] = v;
        } else if (i4 == N4) {
            out[VOCAB - 1] -= lse;               // tail element
        }
    }
}

// ---------------- launch ----------------
extern "C" void kernel_launch(void* const* d_in, const int* in_sizes, int n_in,
                              void* d_out, int out_size) {
    const float* attn  = (const float*)d_in[0];
    const float* x     = (const float*)d_in[1];
    const float* h     = (const float*)d_in[2];
    const float* c     = (const float*)d_in[3];
    const float* W_ih  = (const float*)d_in[4];
    const float* W_hh  = (const float*)d_in[5];
    const float* b_ih  = (const float*)d_in[6];
    const float* b_hh  = (const float*)d_in[7];
    const float* fc1_w = (const float*)d_in[8];
    const float* fc1_b = (const float*)d_in[9];
    const float* fc2_w = (const float*)d_in[10];
    const float* fc2_b = (const float*)d_in[11];
    float* out = (float*)d_out;

    fused_all<<<NBLK, NTHR>>>(attn, x, h, c, W_ih, W_hh, b_ih, b_hh,
                              fc1_w, fc1_b, fc2_w, fc2_b, out);
}